// round 14
// baseline (speedup 1.0000x reference)
#include <cuda_runtime.h>
#include <cstddef>

constexpr int B_   = 8;
constexpr int T_   = 32;
constexpr int NN   = 10;
constexpr int DOBJ = 2048;
constexpr int NV   = 157;
constexpr int NC   = 353;
constexpr int DE   = 512;
constexpr int DV   = 2048;
constexpr int ROWS_PB = T_ * NN;        // 320
constexpr int ROWS = B_ * ROWS_PB;      // 2560
constexpr int OUTW = DE + DV;           // 2560
constexpr int SMAX = 32;                // slot capacity (u ~ 10)
constexpr int SLOTS = 12;
constexpr int GRID = 740;               // <=5 blocks/SM needed; occupancy gives >=6
constexpr int NTHR = 128;

// Packed f32x2 helpers (sm_103a FFMA2 — PTX only)
#define FMA2(acc, a, b) \
    asm("fma.rn.f32x2 %0, %1, %2, %0;" : "+l"(acc) : "l"(a), "l"(b))
#define ADD2(d, a, b) \
    asm("add.rn.f32x2 %0, %1, %2;" : "=l"(d) : "l"(a), "l"(b))
#define PACK_DUP(d, f) \
    asm("mov.b64 %0, {%1, %1};" : "=l"(d) : "r"(__float_as_uint(f)))
#define UNPACK2(lo, hi, v) \
    asm("mov.b64 {%0, %1}, %2;" : "=r"(lo), "=r"(hi) : "l"(v))

// Scratch (static device globals; zero-initialized at load)
__device__ float g_Fc[(size_t)B_ * SMAX * DOBJ];
__device__ float g_H [(size_t)B_ * SMAX * DE];
__device__ int   g_cls[ROWS];
__device__ int   g_count[B_ * NC];      // zeroed by P3 each replay
__device__ int   g_cnt[B_ * SMAX];
__device__ int   g_classlist[B_ * SMAX];
__device__ int   g_sorted[B_ * ROWS_PB];
__device__ int   g_u[B_];
__device__ float g_ctx[B_ * DV];
// Monotonic grid-barrier state (never reset; replay-safe)
__device__ unsigned long long g_tk;
__device__ unsigned long long g_rel;

// Grid-wide barrier: ticket/generation, monotonic counters.
__device__ __forceinline__ void gridbar() {
    __syncthreads();
    if (threadIdx.x == 0) {
        __threadfence();
        unsigned long long t = atomicAdd(&g_tk, 1ULL);
        unsigned long long gen = t / GRID;
        if (t % GRID == GRID - 1) {
            asm volatile("red.release.gpu.global.add.u64 [%0], %1;"
                         :: "l"(&g_rel), "l"(1ULL) : "memory");
        } else {
            unsigned long long r;
            do {
                asm volatile("ld.acquire.gpu.global.u64 %0, [%1];"
                             : "=l"(r) : "l"(&g_rel) : "memory");
                if (r > gen) break;
                __nanosleep(64);
            } while (true);
        }
    }
    __syncthreads();
}

struct PlanS {
    int slotOf[NC];
    int slotCls[SMAX], slotCnt[SMAX];
    int offs[SMAX + 1];
    int rowSlot[ROWS_PB];
};
struct GemS {
    float Fs[256 * 16];                     // 16 KB, transposed [k][16]
    unsigned long long red[4][6][64];       // 12 KB
};
struct ScatS { int ss[20]; };
struct OutS  { float sa[SMAX], sc[SMAX]; };
union SmemU { PlanS plan; GemS gem; ScatS scat; OutS outp; };

__global__ void __launch_bounds__(NTHR, 7)
k_all(const float* __restrict__ feat, const float* __restrict__ fm,
      const int* __restrict__ objid, const float* __restrict__ W,
      const float* __restrict__ bias, const float* __restrict__ Ao2v,
      float* __restrict__ out)
{
    __shared__ SmemU sm;
    __shared__ int s_u;
    int bid = blockIdx.x, tid = threadIdx.x;
    int lane = tid & 31, warp = tid >> 5;

    // ---------------- P0a: ctx mean + class decode + zero Fc/H -------------
    for (int u0 = bid; u0 < 2048; u0 += GRID) {
        if (u0 < 128) {                     // ctx: 16384 elems
            int i = u0 * 128 + tid;
            int b = i / DV, d = i % DV;
            float s = 0.f;
            #pragma unroll
            for (int t = 0; t < T_; t++)
                s += fm[(size_t)(b * T_ + t) * DV + d];
            g_ctx[b * DV + d] = s * (1.f / T_);
        } else if (u0 < 768) {              // cls: 4 rows per unit
            int row = (u0 - 128) * 4 + warp;
            const int* rp = objid + (size_t)row * NC;
            int best = -1;
            for (int i = lane; i < NC; i += 32)
                if (rp[i] != 0) best = i;
            #pragma unroll
            for (int o = 16; o > 0; o >>= 1)
                best = max(best, __shfl_xor_sync(0xffffffffu, best, o));
            int cls = (best < 0) ? 0 : best;
            if (lane == 0) {
                g_cls[row] = cls;
                atomicAdd(&g_count[(row / ROWS_PB) * NC + cls], 1);
            }
        } else if (u0 < 1792) {             // zero Fc: 131072 float4
            ((float4*)g_Fc)[(u0 - 768) * 128 + tid] = make_float4(0, 0, 0, 0);
        } else {                            // zero H: 32768 float4
            ((float4*)g_H)[(u0 - 1792) * 128 + tid] = make_float4(0, 0, 0, 0);
        }
    }
    gridbar();

    // ---------------- P0b: plan (one block per batch; single source) -------
    if (bid < B_) {
        int b = bid;
        if (warp == 0) {
            int run = 0;
            for (int c0 = 0; c0 < NC; c0 += 32) {
                int idx = c0 + lane;
                int cnt = (idx < NC) ? g_count[b * NC + idx] : 0;
                unsigned m = __ballot_sync(0xffffffffu, cnt > 0);
                if (idx < NC) {
                    if (cnt > 0) {
                        int s = run + __popc(m & ((1u << lane) - 1u));
                        sm.plan.slotOf[idx] = s;
                        sm.plan.slotCls[s] = idx;
                        sm.plan.slotCnt[s] = cnt;
                    } else sm.plan.slotOf[idx] = -1;
                }
                run += __popc(m);
            }
            if (lane == 0) {
                s_u = run;
                int acc = 0;
                for (int s = 0; s < run; s++) { sm.plan.offs[s] = acc; acc += sm.plan.slotCnt[s]; }
                sm.plan.offs[run] = acc;
            }
        }
        __syncthreads();
        int u = s_u;
        for (int r = tid; r < ROWS_PB; r += NTHR)
            sm.plan.rowSlot[r] = sm.plan.slotOf[g_cls[b * ROWS_PB + r]];
        __syncthreads();
        for (int r = tid; r < ROWS_PB; r += NTHR) {   // stable deterministic rank
            int s = sm.plan.rowSlot[r];
            int pos = sm.plan.offs[s];
            for (int i = 0; i < r; i++) pos += (sm.plan.rowSlot[i] == s);
            g_sorted[b * ROWS_PB + pos] = (s << 16) | r;
        }
        if (tid == 0) g_u[b] = u;
        for (int s = tid; s < u; s += NTHR) {
            g_classlist[b * SMAX + s] = sm.plan.slotCls[s];
            g_cnt[b * SMAX + s] = sm.plan.slotCnt[s];
        }
    }
    gridbar();

    // ---------------- P1: slot-sorted scatter (512 units) ------------------
    if (bid < 512) {
        int b = bid >> 6, rg = (bid >> 2) & 15, ch = (bid & 3) * 512;
        if (tid < 20) sm.scat.ss[tid] = g_sorted[b * ROWS_PB + rg * 20 + tid];
        __syncthreads();
        const float* fb = feat + (size_t)b * ROWS_PB * DOBJ + ch + tid * 4;
        float4 acc = make_float4(0, 0, 0, 0);
        int cur = sm.scat.ss[0] >> 16;
        #pragma unroll
        for (int r = 0; r < 20; r++) {
            int pk = sm.scat.ss[r];
            int slot = pk >> 16, row = pk & 0xFFFF;
            if (slot != cur) {
                float* dst = g_Fc + ((size_t)b * SMAX + cur) * DOBJ + ch + tid * 4;
                atomicAdd(dst + 0, acc.x); atomicAdd(dst + 1, acc.y);
                atomicAdd(dst + 2, acc.z); atomicAdd(dst + 3, acc.w);
                acc = make_float4(0, 0, 0, 0);
                cur = slot;
            }
            float4 v = *(const float4*)(fb + (size_t)row * DOBJ);
            acc.x += v.x; acc.y += v.y; acc.z += v.z; acc.w += v.w;
        }
        float* dst = g_Fc + ((size_t)b * SMAX + cur) * DOBJ + ch + tid * 4;
        atomicAdd(dst + 0, acc.x); atomicAdd(dst + 1, acc.y);
        atomicAdd(dst + 2, acc.z); atomicAdd(dst + 3, acc.w);
    }
    gridbar();

    // ---------------- P2: FFMA2 GEMM, k-chunks of 256 (512 units) ----------
    if (bid < 512) {
        int b = bid >> 6, kq = (bid >> 3) & 7, colg = (bid & 7) * 64;
        int col = tid & 31, kg = tid >> 5;
        int u = g_u[b];
        for (int g0 = 0; g0 < u; g0 += SLOTS) {
            int ns = min(SLOTS, u - g0);
            for (int j = tid; j < 12 * 64; j += NTHR) {   // transposed Fs load
                int s = j % 12, kk4 = j / 12;
                float4 v = (s < ns)
                    ? ((const float4*)(g_Fc + ((size_t)b * SMAX + g0 + s) * DOBJ + kq * 256))[kk4]
                    : make_float4(0, 0, 0, 0);
                sm.gem.Fs[(kk4 * 4 + 0) * 16 + s] = v.x;
                sm.gem.Fs[(kk4 * 4 + 1) * 16 + s] = v.y;
                sm.gem.Fs[(kk4 * 4 + 2) * 16 + s] = v.z;
                sm.gem.Fs[(kk4 * 4 + 3) * 16 + s] = v.w;
            }
            __syncthreads();

            unsigned long long acc2[6][2];
            #pragma unroll
            for (int p = 0; p < 6; p++) { acc2[p][0] = 0ull; acc2[p][1] = 0ull; }

            const float* Wb = W + (size_t)(kq * 256 + kg * 4) * DE + colg + col * 2;
            #pragma unroll 2
            for (int i = 0; i < 16; i++) {
                #pragma unroll
                for (int j = 0; j < 4; j++) {
                    int krow = kg * 4 + i * 16 + j;
                    float2 w = *(const float2*)&Wb[(size_t)(i * 16 + j) * DE];
                    unsigned long long wp0, wp1;
                    PACK_DUP(wp0, w.x);
                    PACK_DUP(wp1, w.y);
                    const ulonglong2* fp = (const ulonglong2*)&sm.gem.Fs[krow * 16];
                    ulonglong2 q0 = fp[0];
                    ulonglong2 q1 = fp[1];
                    ulonglong2 q2 = fp[2];
                    FMA2(acc2[0][0], q0.x, wp0); FMA2(acc2[0][1], q0.x, wp1);
                    FMA2(acc2[1][0], q0.y, wp0); FMA2(acc2[1][1], q0.y, wp1);
                    FMA2(acc2[2][0], q1.x, wp0); FMA2(acc2[2][1], q1.x, wp1);
                    FMA2(acc2[3][0], q1.y, wp0); FMA2(acc2[3][1], q1.y, wp1);
                    FMA2(acc2[4][0], q2.x, wp0); FMA2(acc2[4][1], q2.x, wp1);
                    FMA2(acc2[5][0], q2.y, wp0); FMA2(acc2[5][1], q2.y, wp1);
                }
            }
            #pragma unroll
            for (int p = 0; p < 6; p++) {
                sm.gem.red[kg][p][col * 2]     = acc2[p][0];
                sm.gem.red[kg][p][col * 2 + 1] = acc2[p][1];
            }
            __syncthreads();
            for (int j = tid; j < 6 * 64; j += NTHR) {
                int p = j >> 6, cidx = j & 63;
                unsigned long long s01, s23, h2;
                ADD2(s01, sm.gem.red[0][p][cidx], sm.gem.red[1][p][cidx]);
                ADD2(s23, sm.gem.red[2][p][cidx], sm.gem.red[3][p][cidx]);
                ADD2(h2, s01, s23);
                unsigned int lo, hi;
                UNPACK2(lo, hi, h2);
                int s0 = 2 * p, s1 = 2 * p + 1;
                if (s0 < ns)
                    atomicAdd(&g_H[((size_t)b * SMAX + g0 + s0) * DE + colg + cidx],
                              __uint_as_float(lo));
                if (s1 < ns)
                    atomicAdd(&g_H[((size_t)b * SMAX + g0 + s1) * DE + colg + cidx],
                              __uint_as_float(hi));
            }
            __syncthreads();
        }
    }
    gridbar();

    // ---------------- P3: assemble output (1256 units) ---------------------
    for (int u0 = bid; u0 < NV * B_; u0 += GRID) {
        int v = u0 / B_, b = u0 % B_;
        int u = g_u[b];
        __syncthreads();
        for (int s = tid; s < u; s += NTHR) {
            sm.outp.sa[s] = Ao2v[(size_t)v * NC + g_classlist[b * SMAX + s]];
            sm.outp.sc[s] = (float)g_cnt[b * SMAX + s];
        }
        if (v == 0)
            for (int i = tid; i < NC; i += NTHR) g_count[b * NC + i] = 0;
        __syncthreads();

        float sbv = 0.f;
        for (int s = 0; s < u; s++) sbv += sm.outp.sa[s] * sm.outp.sc[s];

        float a[4] = {0.f, 0.f, 0.f, 0.f};
        const float* Hb = g_H + (size_t)b * SMAX * DE;
        int s = 0;
        for (; s + 2 <= u; s += 2) {
            float c0 = sm.outp.sa[s], c1 = sm.outp.sa[s + 1];
            const float* H0 = Hb + (size_t)s * DE;
            const float* H1 = H0 + DE;
            #pragma unroll
            for (int q = 0; q < 4; q++) {
                a[q] += c0 * H0[tid + q * 128];
                a[q] += c1 * H1[tid + q * 128];
            }
        }
        if (s < u) {
            float c0 = sm.outp.sa[s];
            const float* H0 = Hb + (size_t)s * DE;
            #pragma unroll
            for (int q = 0; q < 4; q++) a[q] += c0 * H0[tid + q * 128];
        }

        const float inv = 1.f / T_;
        float* orow = out + ((size_t)b * NV + v) * OUTW;
        #pragma unroll
        for (int q = 0; q < 4; q++)
            orow[tid + q * 128] = (a[q] + sbv * bias[tid + q * 128]) * inv;
        const float4* cm = (const float4*)(g_ctx + (size_t)b * DV);
        float4* od = (float4*)(orow + DE);
        #pragma unroll
        for (int q = 0; q < 4; q++) od[tid + q * 128] = cm[tid + q * 128];
    }
}

// ---------------------------------------------------------------------------
extern "C" void kernel_launch(void* const* d_in, const int* in_sizes, int n_in,
                              void* d_out, int out_size) {
    const float* feat  = (const float*)d_in[0];
    const float* fm    = (const float*)d_in[1];
    const int*   objid = (const int*)  d_in[2];
    const float* W     = (const float*)d_in[3];
    const float* bias  = (const float*)d_in[4];
    const float* Ao2v  = (const float*)d_in[5];
    float* out = (float*)d_out;

    k_all<<<GRID, NTHR>>>(feat, fm, objid, W, bias, Ao2v, out);
}

// round 15
// speedup vs baseline: 1.2442x; 1.2442x over previous
#include <cuda_runtime.h>
#include <cuda_bf16.h>
#include <cstddef>

constexpr int B_   = 8;
constexpr int T_   = 32;
constexpr int NN   = 10;
constexpr int DOBJ = 2048;
constexpr int NV   = 157;
constexpr int NC   = 353;
constexpr int DE   = 512;
constexpr int DV   = 2048;
constexpr int ROWS_PB = T_ * NN;         // 320 rows per batch
constexpr int ROWS = B_ * ROWS_PB;       // 2560
constexpr int OUTW = DE + DV;            // 2560
constexpr int NCAP = 320;                // max distinct classes per batch
constexpr int SLOTS = 12;                // slots per hgemm pass
constexpr int RG   = 16;                 // scatter row-groups per batch
constexpr int RPG  = ROWS_PB / RG;       // 20 rows per group (10 per half)
constexpr int KQ   = 16;                 // hgemm k-chunks (128 k each)

// PDL primitives (sm_90+): trigger lets dependent grid launch early; wait
// blocks until the predecessor grid completed and its memory is visible.
#define PDL_TRIGGER() asm volatile("griddepcontrol.launch_dependents;" ::: "memory")
#define PDL_WAIT()    asm volatile("griddepcontrol.wait;" ::: "memory")

// Packed f32x2 helpers (sm_103a FFMA2 path — PTX only, ptxas never auto-fuses)
#define FMA2(acc, a, b) \
    asm("fma.rn.f32x2 %0, %1, %2, %0;" : "+l"(acc) : "l"(a), "l"(b))
#define ADD2(d, a, b) \
    asm("add.rn.f32x2 %0, %1, %2;" : "=l"(d) : "l"(a), "l"(b))
#define PACK_DUP(d, f) \
    asm("mov.b64 %0, {%1, %1};" : "=l"(d) : "r"(__float_as_uint(f)))
#define UNPACK2(lo, hi, v) \
    asm("mov.b64 {%0, %1}, %2;" : "=r"(lo), "=r"(hi) : "l"(v))

// Scratch (static device globals; zero-initialized at load)
__device__ float g_Fc[(size_t)B_ * NCAP * DOBJ];   // compact class-sum features
__device__ float g_H [(size_t)B_ * NCAP * DE];     // Fc @ W (active slots)
__device__ int   g_cls[ROWS];
__device__ int   g_count[B_ * NC];                 // transient; re-zeroed by k_plan
__device__ int   g_cnt[B_ * NCAP];                 // compact per-slot counts
__device__ int   g_classlist[B_ * NC];
__device__ int   g_sorted[B_ * ROWS_PB];           // (slot<<16)|row, sorted by slot
__device__ int   g_u[B_];
__device__ float g_ctx[B_ * DV];

// ---------------------------------------------------------------------------
// K0: fused — blocks [0,64): temporal mean of fm_context
//             blocks [64,384): per-row class decode (warp per row)
__global__ void k_precls(const float* __restrict__ fm,
                         const int* __restrict__ obj_id) {  // grid 384, block 256
    PDL_TRIGGER();                 // let k_plan's blocks stage early
    if (blockIdx.x < 64) {
        int i = blockIdx.x * 256 + threadIdx.x;      // B_*DV = 16384
        int b = i / DV, d = i % DV;
        float s = 0.f;
        #pragma unroll
        for (int t = 0; t < T_; t++)
            s += fm[((size_t)(b * T_ + t)) * DV + d];
        g_ctx[b * DV + d] = s * (1.f / T_);
    } else {
        int blk = blockIdx.x - 64;                    // 320 blocks, 8 warps each
        int warp = blk * 8 + (threadIdx.x >> 5);      // row id 0..2559
        int lane = threadIdx.x & 31;
        const int* row = obj_id + (size_t)warp * NC;
        int best = -1;
        #pragma unroll
        for (int i = lane; i < NC; i += 32)
            if (row[i] != 0) best = i;
        #pragma unroll
        for (int o = 16; o > 0; o >>= 1)
            best = max(best, __shfl_xor_sync(0xffffffffu, best, o));
        int cls = (best < 0) ? 0 : best;
        if (lane == 0) {
            g_cls[warp] = cls;
            int b = warp / ROWS_PB;
            atomicAdd(&g_count[b * NC + cls], 1);
        }
    }
}

// ---------------------------------------------------------------------------
// K1: per-batch plan: compact class list, counting-sort rows by slot,
// compact counts, restore g_count to zero, zero active Fc/H rows.
__global__ void k_plan() {   // grid B_, block 384
    PDL_TRIGGER();
    PDL_WAIT();                // needs k_precls's g_count/g_cls
    int b = blockIdx.x, tid = threadIdx.x;
    int w = tid >> 5, lane = tid & 31;
    __shared__ int wc[12], base[12], u_s;
    __shared__ int slotOf[NC];
    __shared__ int offs[NCAP];

    int cnt = (tid < NC) ? g_count[b * NC + tid] : 0;
    unsigned mask = __ballot_sync(0xffffffffu, cnt > 0);
    if (lane == 0) wc[w] = __popc(mask);
    __syncthreads();
    if (tid == 0) {
        int run = 0;
        for (int i = 0; i < 12; i++) { base[i] = run; run += wc[i]; }
        u_s = run; g_u[b] = run;
    }
    __syncthreads();
    if (cnt > 0) {
        int slot = base[w] + __popc(mask & ((1u << lane) - 1u));
        g_classlist[b * NC + slot] = tid;
        g_cnt[b * NCAP + slot] = cnt;
        slotOf[tid] = slot;
        g_count[b * NC + tid] = 0;        // restore zero state for next replay
    } else if (tid < NC) slotOf[tid] = -1;
    __syncthreads();
    int u = u_s;
    if (tid == 0) {  // slot start offsets
        int run = 0;
        for (int s = 0; s < u; s++) { offs[s] = run; run += g_cnt[b * NCAP + s]; }
    }
    __syncthreads();
    if (tid < ROWS_PB) {  // counting sort of rows by slot
        int cls = g_cls[b * ROWS_PB + tid];
        int s = slotOf[cls];
        int pos = atomicAdd(&offs[s], 1);
        g_sorted[b * ROWS_PB + pos] = (s << 16) | tid;
    }
    // zero active scratch: u rows of Fc (2048) and H (512)
    float4* pF = (float4*)(g_Fc + (size_t)b * NCAP * DOBJ);
    for (int i = tid; i < u * (DOBJ / 4); i += 384) pF[i] = make_float4(0,0,0,0);
    float4* pH = (float4*)(g_H + (size_t)b * NCAP * DE);
    for (int i = tid; i < u * (DE / 4); i += 384) pH[i] = make_float4(0,0,0,0);
}

// ---------------------------------------------------------------------------
// K2: slot-sorted scatter, 16 row-groups per batch for parallelism.
__global__ void k_scatter(const float* __restrict__ feat) {
    // grid (DOBJ/512=4, RG=16, B_), block 256
    PDL_TRIGGER();
    PDL_WAIT();                // needs k_plan's g_sorted and zeroed g_Fc
    int b = blockIdx.z, rg = blockIdx.y;
    int ch = blockIdx.x * 512;
    int tid = threadIdx.x;
    int half = tid >> 7;          // 2 halves of RPG/2 = 10 rows
    int l = tid & 127;            // 128 threads x float4 = 512 floats

    __shared__ int s_sorted[RPG];
    if (tid < RPG) s_sorted[tid] = g_sorted[b * ROWS_PB + rg * RPG + tid];
    __syncthreads();

    const float* fbase = feat + (size_t)b * ROWS_PB * DOBJ + ch + l * 4;
    int r = half * (RPG / 2), end = r + (RPG / 2);
    float4 acc = make_float4(0, 0, 0, 0);
    int cur = s_sorted[r] >> 16;
    #pragma unroll
    for (; r < end; r++) {
        int pk = s_sorted[r];
        int slot = pk >> 16, row = pk & 0xFFFF;
        if (slot != cur) {
            float* dst = g_Fc + ((size_t)b * NCAP + cur) * DOBJ + ch + l * 4;
            atomicAdd(dst + 0, acc.x); atomicAdd(dst + 1, acc.y);
            atomicAdd(dst + 2, acc.z); atomicAdd(dst + 3, acc.w);
            acc = make_float4(0, 0, 0, 0);
            cur = slot;
        }
        float4 v = *(const float4*)(fbase + (size_t)row * DOBJ);
        acc.x += v.x; acc.y += v.y; acc.z += v.z; acc.w += v.w;
    }
    float* dst = g_Fc + ((size_t)b * NCAP + cur) * DOBJ + ch + l * 4;
    atomicAdd(dst + 0, acc.x); atomicAdd(dst + 1, acc.y);
    atomicAdd(dst + 2, acc.z); atomicAdd(dst + 3, acc.w);
}

// ---------------------------------------------------------------------------
// K3: H[b,slot,:] += Fc[b,slot,kq*128:+128] @ W[kq*128:+128,:]
// grid (DE/64=8 colg, KQ=16, B_), block 128 (32 col-lanes x 4 kg).
// Packed-math: Fs TRANSPOSED [k][16] so ulonglong2 LDS.128 yields slot-pairs
// pre-packed for fma.rn.f32x2 (FFMA2). Best-measured hgemm variant (R9).
__global__ void __launch_bounds__(128, 8) k_hgemm(const float* __restrict__ W) {
    PDL_TRIGGER();
    PDL_WAIT();                // needs k_scatter's g_Fc
    __shared__ float Fs[128][16];                         // transposed, padded: 8 KB
    __shared__ unsigned long long red[4][6][64];          // packed partials: 12 KB
    int b = blockIdx.z;
    int kq = blockIdx.y;
    int colg = blockIdx.x * 64;
    int tid = threadIdx.x;
    int col = tid & 31;           // lane -> cols colg + 2*col, +1
    int kg = tid >> 5;            // 0..3
    int u = g_u[b];

    for (int g0 = 0; g0 < u; g0 += SLOTS) {
        int ns = min(SLOTS, u - g0);
        // transposed cooperative load: j -> (slot s, 4k-group kk4)
        for (int j = tid; j < SLOTS * 32; j += 128) {
            int s = j % 12, kk4 = j / 12;
            float4 v = (s < ns)
                ? ((const float4*)(g_Fc + ((size_t)b * NCAP + g0 + s) * DOBJ + kq * 128))[kk4]
                : make_float4(0, 0, 0, 0);
            Fs[kk4 * 4 + 0][s] = v.x;
            Fs[kk4 * 4 + 1][s] = v.y;
            Fs[kk4 * 4 + 2][s] = v.z;
            Fs[kk4 * 4 + 3][s] = v.w;
        }
        __syncthreads();

        unsigned long long acc2[6][2];
        #pragma unroll
        for (int p = 0; p < 6; p++) { acc2[p][0] = 0ull; acc2[p][1] = 0ull; }

        // this thread's k: kg*4 + i*16 + j, i<8, j<4
        const float* Wb = W + (size_t)(kq * 128 + kg * 4) * DE + colg + col * 2;
        #pragma unroll 2
        for (int i = 0; i < 8; i++) {
            #pragma unroll
            for (int j = 0; j < 4; j++) {
                int krow = kg * 4 + i * 16 + j;
                float2 w = *(const float2*)&Wb[(size_t)(i * 16 + j) * DE];
                unsigned long long wp0, wp1;
                PACK_DUP(wp0, w.x);
                PACK_DUP(wp1, w.y);
                const ulonglong2* fp = (const ulonglong2*)&Fs[krow][0];
                ulonglong2 q0 = fp[0];   // slots 0-3 (2 packed pairs)
                ulonglong2 q1 = fp[1];   // slots 4-7
                ulonglong2 q2 = fp[2];   // slots 8-11
                FMA2(acc2[0][0], q0.x, wp0); FMA2(acc2[0][1], q0.x, wp1);
                FMA2(acc2[1][0], q0.y, wp0); FMA2(acc2[1][1], q0.y, wp1);
                FMA2(acc2[2][0], q1.x, wp0); FMA2(acc2[2][1], q1.x, wp1);
                FMA2(acc2[3][0], q1.y, wp0); FMA2(acc2[3][1], q1.y, wp1);
                FMA2(acc2[4][0], q2.x, wp0); FMA2(acc2[4][1], q2.x, wp1);
                FMA2(acc2[5][0], q2.y, wp0); FMA2(acc2[5][1], q2.y, wp1);
            }
        }

        #pragma unroll
        for (int p = 0; p < 6; p++) {
            red[kg][p][col * 2]     = acc2[p][0];
            red[kg][p][col * 2 + 1] = acc2[p][1];
        }
        __syncthreads();
        for (int j = tid; j < 6 * 64; j += 128) {   // 3 iters
            int p = j >> 6, cidx = j & 63;
            unsigned long long s01, s23, h2;
            ADD2(s01, red[0][p][cidx], red[1][p][cidx]);
            ADD2(s23, red[2][p][cidx], red[3][p][cidx]);
            ADD2(h2, s01, s23);
            unsigned int lo, hi;
            UNPACK2(lo, hi, h2);
            int s0 = 2 * p, s1 = 2 * p + 1;
            if (s0 < ns)
                atomicAdd(&g_H[((size_t)b * NCAP + g0 + s0) * DE + colg + cidx],
                          __uint_as_float(lo));
            if (s1 < ns)
                atomicAdd(&g_H[((size_t)b * NCAP + g0 + s1) * DE + colg + cidx],
                          __uint_as_float(hi));
        }
        __syncthreads();
    }
}

// ---------------------------------------------------------------------------
// K4: assemble output rows (smem-staged coefficients; R11-measured variant).
__global__ void k_out(const float* __restrict__ Ao2v,
                      const float* __restrict__ bias,
                      float* __restrict__ out) {  // grid (NV, B_), 256
    PDL_WAIT();                // needs k_hgemm's g_H (and earlier plan/ctx)
    int v = blockIdx.x, b = blockIdx.y;
    int tid = threadIdx.x;
    int u = g_u[b];
    __shared__ float sa[NCAP];   // per-slot Ao2v coefficient
    __shared__ float sc[NCAP];   // per-slot count (as float)

    for (int s = tid; s < u; s += 256) {
        int c = g_classlist[b * NC + s];
        sa[s] = Ao2v[(size_t)v * NC + c];
        sc[s] = (float)g_cnt[b * NCAP + s];
    }
    __syncthreads();

    float sbv = 0.f;
    for (int s = 0; s < u; s++) sbv += sa[s] * sc[s];

    float a0 = 0.f, a1 = 0.f;
    const float* Hb = g_H + (size_t)b * NCAP * DE;
    int s = 0;
    for (; s + 2 <= u; s += 2) {
        float c0 = sa[s], c1 = sa[s + 1];
        const float* H0 = Hb + (size_t)(s + 0) * DE;
        const float* H1 = Hb + (size_t)(s + 1) * DE;
        float h00 = H0[tid], h01 = H0[tid + 256];
        float h10 = H1[tid], h11 = H1[tid + 256];
        a0 += c0 * h00; a1 += c0 * h01;
        a0 += c1 * h10; a1 += c1 * h11;
    }
    if (s < u) {
        float c0 = sa[s];
        const float* H0 = Hb + (size_t)s * DE;
        a0 += c0 * H0[tid];
        a1 += c0 * H0[tid + 256];
    }

    const float inv = 1.f / T_;
    float* orow = out + ((size_t)b * NV + v) * OUTW;
    orow[tid]       = (a0 + sbv * bias[tid]) * inv;
    orow[tid + 256] = (a1 + sbv * bias[tid + 256]) * inv;
    const float4* cm = (const float4*)(g_ctx + (size_t)b * DV);
    float4* od = (float4*)(orow + DE);
    #pragma unroll
    for (int j = tid; j < DV / 4; j += 256) od[j] = cm[j];
}

// ---------------------------------------------------------------------------
template <typename... Args>
static inline void launch_pdl(void (*kern)(Args...), dim3 grid, dim3 block,
                              Args... args) {
    cudaLaunchConfig_t cfg = {};
    cfg.gridDim = grid;
    cfg.blockDim = block;
    cfg.dynamicSmemBytes = 0;
    cfg.stream = 0;
    cudaLaunchAttribute attr[1];
    attr[0].id = cudaLaunchAttributeProgrammaticStreamSerialization;
    attr[0].val.programmaticStreamSerializationAllowed = 1;
    cfg.attrs = attr;
    cfg.numAttrs = 1;
    cudaLaunchKernelEx(&cfg, kern, args...);
}

extern "C" void kernel_launch(void* const* d_in, const int* in_sizes, int n_in,
                              void* d_out, int out_size) {
    const float* feat  = (const float*)d_in[0];
    const float* fm    = (const float*)d_in[1];
    const int*   objid = (const int*)  d_in[2];
    const float* W     = (const float*)d_in[3];
    const float* bias  = (const float*)d_in[4];
    const float* Ao2v  = (const float*)d_in[5];
    float* out = (float*)d_out;

    // First kernel: normal launch. All dependents opt into PDL so their
    // blocks stage early and wait in HW instead of paying launch ramp.
    k_precls<<<384, 256>>>(fm, objid);
    launch_pdl(k_plan, dim3(B_), dim3(384));
    launch_pdl(k_scatter, dim3(DOBJ / 512, RG, B_), dim3(256), feat);
    launch_pdl(k_hgemm, dim3(DE / 64, KQ, B_), dim3(128), W);
    launch_pdl(k_out, dim3(NV, B_), dim3(256), Ao2v, bias, out);
}